// round 3
// baseline (speedup 1.0000x reference)
#include <cuda_runtime.h>
#include <cstdint>

#define H    512
#define G4   2048
#define SEQL 1024
#define EMB  300
#define NCTA 128     // one CTA per hidden-unit group of 4; all co-resident (<148 SMs)
#define TPB  128     // 4 warps; warp w owns hidden unit b*4+w (all four gates)

// Scratch (no allocations allowed): 8 MB gate-precompute + 4 MB tagged-h ring.
__device__ float              g_xg[SEQL * G4];
__device__ unsigned long long g_htag[SEQL * H];

// ---------------------------------------------------------------------------
// Kernel 1: xg[t][row] = (b_ih[row]+b_hh[row]) + sum_e emb[tok[t]][e]*W_ih[row][e]
// 64x64 output tile per block, 4x4 micro-tile per thread, K-chunks of 16.
// ---------------------------------------------------------------------------
#define TK 16
__global__ __launch_bounds__(256) void xgemm_kernel(
    const int* __restrict__ tokens,
    const float* __restrict__ emb,
    const float* __restrict__ Wih,
    const float* __restrict__ bih,
    const float* __restrict__ bhh)
{
    __shared__ float Ws[64][TK + 1];
    __shared__ float Xs[64][TK + 1];
    __shared__ int   toks[64];

    const int row0 = blockIdx.x * 64;
    const int t0   = blockIdx.y * 64;
    const int tid  = threadIdx.x;
    const int tx = tid & 15, ty = tid >> 4;

    if (tid < 64) toks[tid] = tokens[t0 + tid];
    __syncthreads();

    float acc[4][4];
#pragma unroll
    for (int i = 0; i < 4; i++)
#pragma unroll
        for (int j = 0; j < 4; j++) acc[i][j] = 0.f;

    const int kk = tid & 15;
    const int ib = tid >> 4;

    for (int k0 = 0; k0 < EMB; k0 += TK) {
#pragma unroll
        for (int q = 0; q < 4; q++) {
            int i = ib + q * 16;
            int e = k0 + kk;
            long widx = (long)(row0 + i) * EMB + (e < EMB ? e : EMB - 1);
            Ws[i][kk] = Wih[widx];
            Xs[i][kk] = (e < EMB) ? emb[(long)toks[i] * EMB + e] : 0.f;
        }
        __syncthreads();
#pragma unroll
        for (int k = 0; k < TK; k++) {
            float a[4], x[4];
#pragma unroll
            for (int i = 0; i < 4; i++) a[i] = Ws[tx * 4 + i][k];
#pragma unroll
            for (int j = 0; j < 4; j++) x[j] = Xs[ty * 4 + j][k];
#pragma unroll
            for (int i = 0; i < 4; i++)
#pragma unroll
                for (int j = 0; j < 4; j++)
                    acc[i][j] += a[i] * x[j];
        }
        __syncthreads();
    }

#pragma unroll
    for (int i = 0; i < 4; i++) {
        int row = row0 + tx * 4 + i;
        float bias = bih[row] + bhh[row];
#pragma unroll
        for (int j = 0; j < 4; j++) {
            int t = t0 + ty * 4 + j;
            g_xg[(long)t * G4 + row] = acc[i][j] + bias;
        }
    }
}

// ---------------------------------------------------------------------------
// packed fp32x2 FMA (sm_103a; ptxas never emits it from C++, only via PTX)
// ---------------------------------------------------------------------------
__device__ __forceinline__ void ffma2(unsigned long long& d,
                                      unsigned long long a,
                                      unsigned long long b)
{
    asm("fma.rn.f32x2 %0, %1, %2, %3;" : "=l"(d) : "l"(a), "l"(b), "l"(d));
}

__device__ __forceinline__ float fast_tanh(float x)
{
    float a = fabsf(x);
    float e = __expf(-2.f * a);
    float r = __fdividef(1.f - e, 1.f + e);
    return copysignf(r, x);
}
__device__ __forceinline__ float fast_sigmoid(float x)
{
    return __fdividef(1.f, 1.f + __expf(-x));
}

// ---------------------------------------------------------------------------
// Kernel 2: persistent LSTM recurrence.
// 128 CTAs x 128 threads (1 warp/SMSP). Warp w of CTA b owns hidden unit
// u = 4b + w: all four gate rows {g*512 + u}. W_hh entirely in registers
// (64 fp32/thread packed as 32 f32x2). Per step:
//   phase A: each thread polls its 4 tagged h values -> smem double buffer
//   __syncthreads (the ONLY barrier; double-buffer safety is transitive:
//     poll success at t => some CTA's barrier at t-1 => all 512 tags t-1
//     => every warp finished reading buffer (t-2)&1 == t&1)
//   phase B: 4 rows x 16 K per thread via f32x2, xor-butterfly, lane0 does
//     nonlinearity + PAD select + tagged publish. No trailing barrier.
// ---------------------------------------------------------------------------
__global__ __launch_bounds__(TPB, 1) void lstm_kernel(
    const int* __restrict__ tokens,
    const float* __restrict__ h0,
    const float* __restrict__ c0,
    const float* __restrict__ Whh,
    float* __restrict__ out)
{
    __shared__ __align__(16) float h_buf[2][H];
    __shared__ int toks[SEQL];

    const int b    = blockIdx.x;
    const int tid  = threadIdx.x;
    const int w    = tid >> 5;
    const int lane = tid & 31;
    const int u    = b * 4 + w;          // hidden unit owned by this warp

    for (int i = tid; i < SEQL; i += TPB) toks[i] = tokens[i];

    // Weight pairs: row g*H+u, K-pairs at {2*lane + 64*j, +1}, j=0..7.
    unsigned long long wp[4][8];
#pragma unroll
    for (int g = 0; g < 4; g++) {
        const float* wrow = Whh + (long)(g * H + u) * H;
#pragma unroll
        for (int j = 0; j < 8; j++) {
            float2 f = *(const float2*)(wrow + 2 * lane + 64 * j);
            unsigned long long v;
            asm("mov.b64 %0, {%1,%2};" : "=l"(v) : "f"(f.x), "f"(f.y));
            wp[g][j] = v;
        }
    }

    float c_reg = 0.f, h_last = 0.f, out_reg = 0.f;
    if (lane == 0) { c_reg = c0[u]; h_last = h0[u]; }

    unsigned long long* htag = g_htag;

    for (int t = 0; t < SEQL; t++) {
        // xg prefetch for this warp's 4 gate rows (independent of h).
        float xgv0 = 0.f, xgv1 = 0.f, xgv2 = 0.f, xgv3 = 0.f;
        if (lane == 0) {
            const float* xr = g_xg + (long)t * G4 + u;
            xgv0 = xr[0];  xgv1 = xr[H];  xgv2 = xr[2 * H];  xgv3 = xr[3 * H];
        }

        const int p = t & 1;
        if (t == 0) {
            *(float4*)&h_buf[p][4 * tid] = *(const float4*)(h0 + 4 * tid);
        } else {
            const unsigned long long* ptr = htag + (size_t)(t - 1) * H + 4 * tid;
            unsigned long long v0, v1, v2, v3;
            const unsigned tag = (unsigned)t;
            do {
                asm volatile("ld.volatile.global.v2.u64 {%0,%1},[%2];"
                             : "=l"(v0), "=l"(v1) : "l"(ptr));
                asm volatile("ld.volatile.global.v2.u64 {%0,%1},[%2];"
                             : "=l"(v2), "=l"(v3) : "l"(ptr + 2));
            } while ((unsigned)(v0 >> 32) != tag || (unsigned)(v1 >> 32) != tag ||
                     (unsigned)(v2 >> 32) != tag || (unsigned)(v3 >> 32) != tag);
            float4 hv;
            hv.x = __uint_as_float((unsigned)v0);
            hv.y = __uint_as_float((unsigned)v1);
            hv.z = __uint_as_float((unsigned)v2);
            hv.w = __uint_as_float((unsigned)v3);
            *(float4*)&h_buf[p][4 * tid] = hv;
        }
        __syncthreads();

        // 4 gate rows x 16 K-elements per thread, weights in regs, f32x2 FMA.
        unsigned long long a0 = 0ull, a1 = 0ull, a2 = 0ull, a3 = 0ull;
        const unsigned long long* hb =
            (const unsigned long long*)&h_buf[p][2 * lane];
#pragma unroll
        for (int j = 0; j < 8; j++) {
            unsigned long long hv = hb[32 * j];    // h[2*lane+64j], h[+1]
            ffma2(a0, wp[0][j], hv);
            ffma2(a1, wp[1][j], hv);
            ffma2(a2, wp[2][j], hv);
            ffma2(a3, wp[3][j], hv);
        }
        float acc0, acc1, acc2, acc3;
        {
            float lo, hi;
            asm("mov.b64 {%0,%1}, %2;" : "=f"(lo), "=f"(hi) : "l"(a0)); acc0 = lo + hi;
            asm("mov.b64 {%0,%1}, %2;" : "=f"(lo), "=f"(hi) : "l"(a1)); acc1 = lo + hi;
            asm("mov.b64 {%0,%1}, %2;" : "=f"(lo), "=f"(hi) : "l"(a2)); acc2 = lo + hi;
            asm("mov.b64 {%0,%1}, %2;" : "=f"(lo), "=f"(hi) : "l"(a3)); acc3 = lo + hi;
        }
#pragma unroll
        for (int off = 16; off > 0; off >>= 1) {
            acc0 += __shfl_xor_sync(0xffffffffu, acc0, off);
            acc1 += __shfl_xor_sync(0xffffffffu, acc1, off);
            acc2 += __shfl_xor_sync(0xffffffffu, acc2, off);
            acc3 += __shfl_xor_sync(0xffffffffu, acc3, off);
        }

        if (lane == 0) {
            float si = fast_sigmoid(acc0 + xgv0);
            float sf = fast_sigmoid(acc1 + xgv1);
            float tg = fast_tanh   (acc2 + xgv2);
            float so = fast_sigmoid(acc3 + xgv3);
            float c_new = sf * c_reg + si * tg;
            float h_new = so * fast_tanh(c_new);
            if (toks[t] != 1) {                 // PAD_IDX == 1
                c_reg  = c_new;
                h_last = h_new;
                out_reg = h_new;
            }
            unsigned long long v =
                ((unsigned long long)(unsigned)(t + 1) << 32) |
                (unsigned long long)__float_as_uint(h_last);
            htag[(size_t)t * H + u] = v;
        }
        // no trailing barrier: double buffer + barrier-transitivity (see header)
    }

    if (lane == 0) {
        out[u]         = out_reg;  // out
        out[H + u]     = h_last;   // h
        out[2 * H + u] = c_reg;    // c
    }
}

extern "C" void kernel_launch(void* const* d_in, const int* in_sizes, int n_in,
                              void* d_out, int out_size)
{
    const int*   tokens = (const int*)  d_in[0];
    const float* h0     = (const float*)d_in[1];
    const float* c0     = (const float*)d_in[2];
    const float* emb    = (const float*)d_in[3];
    const float* Wih    = (const float*)d_in[4];
    const float* Whh    = (const float*)d_in[5];
    const float* bih    = (const float*)d_in[6];
    const float* bhh    = (const float*)d_in[7];
    float* out = (float*)d_out;

    // Reset the tag buffer every launch (deterministic across graph replays).
    void* htag_ptr = nullptr;
    cudaGetSymbolAddress(&htag_ptr, g_htag);
    cudaMemsetAsync(htag_ptr, 0, sizeof(unsigned long long) * SEQL * H);

    dim3 g1(G4 / 64, SEQL / 64);
    xgemm_kernel<<<g1, 256>>>(tokens, emb, Wih, bih, bhh);
    lstm_kernel<<<NCTA, TPB>>>(tokens, h0, c0, Whh, out);
}

// round 4
// speedup vs baseline: 1.4524x; 1.4524x over previous
#include <cuda_runtime.h>
#include <cstdint>

#define H    512
#define G4   2048
#define SEQL 1024
#define EMB  300
#define NCTA 64      // proven co-resident config (R1)
#define TPB  256     // 8 warps; warp w owns hidden unit u = 8b + w

// Scratch: 8 MB gate-precompute (transposed [t][u][gate]) + 4 MB tagged-h ring.
__device__ float g_xg4[SEQL * G4];
__device__ __align__(16) unsigned long long g_htag[SEQL * H];

// ---------------------------------------------------------------------------
// Kernel 1: xg[t][u][g] = (b_ih[r]+b_hh[r]) + sum_e emb[tok[t]][e]*W_ih[r][e],
// r = g*512+u. 64x64 tile per block, 4x4 micro-tile per thread.
// ---------------------------------------------------------------------------
#define TK 16
__global__ __launch_bounds__(256) void xgemm_kernel(
    const int* __restrict__ tokens,
    const float* __restrict__ emb,
    const float* __restrict__ Wih,
    const float* __restrict__ bih,
    const float* __restrict__ bhh)
{
    __shared__ float Ws[64][TK + 1];
    __shared__ float Xs[64][TK + 1];
    __shared__ int   toks[64];

    const int row0 = blockIdx.x * 64;
    const int t0   = blockIdx.y * 64;
    const int tid  = threadIdx.x;
    const int tx = tid & 15, ty = tid >> 4;

    if (tid < 64) toks[tid] = tokens[t0 + tid];
    __syncthreads();

    float acc[4][4];
#pragma unroll
    for (int i = 0; i < 4; i++)
#pragma unroll
        for (int j = 0; j < 4; j++) acc[i][j] = 0.f;

    const int kk = tid & 15;
    const int ib = tid >> 4;

    for (int k0 = 0; k0 < EMB; k0 += TK) {
#pragma unroll
        for (int q = 0; q < 4; q++) {
            int i = ib + q * 16;
            int e = k0 + kk;
            long widx = (long)(row0 + i) * EMB + (e < EMB ? e : EMB - 1);
            Ws[i][kk] = Wih[widx];
            Xs[i][kk] = (e < EMB) ? emb[(long)toks[i] * EMB + e] : 0.f;
        }
        __syncthreads();
#pragma unroll
        for (int k = 0; k < TK; k++) {
            float a[4], x[4];
#pragma unroll
            for (int i = 0; i < 4; i++) a[i] = Ws[tx * 4 + i][k];
#pragma unroll
            for (int j = 0; j < 4; j++) x[j] = Xs[ty * 4 + j][k];
#pragma unroll
            for (int i = 0; i < 4; i++)
#pragma unroll
                for (int j = 0; j < 4; j++)
                    acc[i][j] += a[i] * x[j];
        }
        __syncthreads();
    }

#pragma unroll
    for (int i = 0; i < 4; i++) {
        int row = row0 + tx * 4 + i;
        float bias = bih[row] + bhh[row];
        int u = row & 511, g = row >> 9;
#pragma unroll
        for (int j = 0; j < 4; j++) {
            int t = t0 + ty * 4 + j;
            g_xg4[(long)t * G4 + u * 4 + g] = acc[i][j] + bias;   // [t][u][gate]
        }
    }
}

// ---------------------------------------------------------------------------
// packed fp32x2 ops (sm_103a; ptxas won't emit from C++)
// ---------------------------------------------------------------------------
__device__ __forceinline__ void ffma2(unsigned long long& d,
                                      unsigned long long a, unsigned long long b)
{
    asm("fma.rn.f32x2 %0, %1, %2, %3;" : "=l"(d) : "l"(a), "l"(b), "l"(d));
}
__device__ __forceinline__ void fadd2(unsigned long long& d,
                                      unsigned long long a, unsigned long long b)
{
    asm("add.rn.f32x2 %0, %1, %2;" : "=l"(d) : "l"(a), "l"(b));
}

__device__ __forceinline__ float fast_tanh(float x)
{
    float a = fabsf(x);
    float e = __expf(-2.f * a);
    float r = __fdividef(1.f - e, 1.f + e);
    return copysignf(r, x);
}
__device__ __forceinline__ float fast_sigmoid(float x)
{
    return __fdividef(1.f, 1.f + __expf(-x));
}

// ---------------------------------------------------------------------------
// Kernel 2: persistent LSTM recurrence.
// 64 CTAs x 256 threads. Warp w of CTA b owns hidden unit u = 8b + w.
// Within a warp, the 8-lane quarter g = lane>>3 computes gate row g*512+u:
// 64 weights/thread as 32 f32x2 in registers. Per step:
//   prefetch xg float4 -> poll h_{t-1} (2 tagged u64 / thread, with ~220-cyc
//   clock-backoff to avoid LTS flood) -> smem double buffer -> ONE barrier ->
//   f32x2 dot -> 3-level xor-shfl reduce -> lane0 gathers 4 gate sums,
//   nonlinearity, PAD select, tagged publish. No trailing barrier
//   (double buffer + barrier transitivity).
// ---------------------------------------------------------------------------
__global__ __launch_bounds__(TPB, 1) void lstm_kernel(
    const int* __restrict__ tokens,
    const float* __restrict__ h0,
    const float* __restrict__ c0,
    const float* __restrict__ Whh,
    float* __restrict__ out)
{
    __shared__ __align__(16) float h_buf[2][H];
    __shared__ int toks[SEQL];

    const int b    = blockIdx.x;
    const int tid  = threadIdx.x;
    const int w    = tid >> 5;
    const int lane = tid & 31;
    const int g    = lane >> 3;          // gate handled by this lane
    const int q    = lane & 7;           // K-slot within gate group
    const int u    = b * 8 + w;          // hidden unit owned by this warp

    for (int i = tid; i < SEQL; i += TPB) toks[i] = tokens[i];

    // Weights for gate row g*H+u: pairs k = 2*q + 16*j, j = 0..31.
    unsigned long long wp[32];
    {
        const float* wrow = Whh + (size_t)(g * H + u) * H;
#pragma unroll
        for (int j = 0; j < 32; j++) {
            float2 f = *(const float2*)(wrow + 2 * q + 16 * j);
            unsigned long long v;
            asm("mov.b64 %0, {%1,%2};" : "=l"(v) : "f"(f.x), "f"(f.y));
            wp[j] = v;
        }
    }

    float c_reg = 0.f, h_last = 0.f, out_reg = 0.f;
    if (lane == 0) { c_reg = c0[u]; h_last = h0[u]; }

    unsigned long long* htag = g_htag;

    for (int t = 0; t < SEQL; t++) {
        // Prefetch this unit's 4 gate biases: single LDG.128 (independent of h).
        float4 xgv = make_float4(0.f, 0.f, 0.f, 0.f);
        if (lane == 0)
            xgv = *(const float4*)(g_xg4 + (size_t)t * G4 + u * 4);

        const int p = t & 1;
        if (t == 0) {
            *(float2*)&h_buf[p][2 * tid] = *(const float2*)(h0 + 2 * tid);
        } else {
            const unsigned long long* ptr = htag + (size_t)(t - 1) * H + 2 * tid;
            unsigned long long v0, v1;
            const unsigned tag = (unsigned)t;
            for (;;) {
                asm volatile("ld.volatile.global.v2.u64 {%0,%1},[%2];"
                             : "=l"(v0), "=l"(v1) : "l"(ptr));
                if ((unsigned)(v0 >> 32) == tag && (unsigned)(v1 >> 32) == tag)
                    break;
                // local backoff: keep the LTS queues shallow while waiting
                unsigned s = (unsigned)clock();
                while ((unsigned)clock() - s < 220u) { }
            }
            float2 hv;
            hv.x = __uint_as_float((unsigned)v0);
            hv.y = __uint_as_float((unsigned)v1);
            *(float2*)&h_buf[p][2 * tid] = hv;
        }
        __syncthreads();   // the only barrier per step

        // Dot: 64 weights x h via 32 f32x2, 4 interleaved accumulators.
        unsigned long long a0 = 0ull, a1 = 0ull, a2 = 0ull, a3 = 0ull;
        const unsigned long long* hb =
            (const unsigned long long*)&h_buf[p][2 * q];
#pragma unroll
        for (int j = 0; j < 32; j += 4) {
            ffma2(a0, wp[j + 0], hb[8 * (j + 0)]);
            ffma2(a1, wp[j + 1], hb[8 * (j + 1)]);
            ffma2(a2, wp[j + 2], hb[8 * (j + 2)]);
            ffma2(a3, wp[j + 3], hb[8 * (j + 3)]);
        }
        fadd2(a0, a0, a1);
        fadd2(a2, a2, a3);
        fadd2(a0, a0, a2);
        float lo, hi;
        asm("mov.b64 {%0,%1}, %2;" : "=f"(lo), "=f"(hi) : "l"(a0));
        float acc = lo + hi;

        // Reduce across the 8-lane gate group (xor stays within the group).
        acc += __shfl_xor_sync(0xffffffffu, acc, 4);
        acc += __shfl_xor_sync(0xffffffffu, acc, 2);
        acc += __shfl_xor_sync(0xffffffffu, acc, 1);

        // Gather the four gate sums (held by lanes 0, 8, 16, 24) to lane 0.
        float s_i = __shfl_sync(0xffffffffu, acc, 0);
        float s_f = __shfl_sync(0xffffffffu, acc, 8);
        float s_g = __shfl_sync(0xffffffffu, acc, 16);
        float s_o = __shfl_sync(0xffffffffu, acc, 24);

        if (lane == 0) {
            float si = fast_sigmoid(s_i + xgv.x);
            float sf = fast_sigmoid(s_f + xgv.y);
            float tg = fast_tanh   (s_g + xgv.z);
            float so = fast_sigmoid(s_o + xgv.w);
            float c_new = sf * c_reg + si * tg;
            float h_new = so * fast_tanh(c_new);
            if (toks[t] != 1) {                 // PAD_IDX == 1
                c_reg  = c_new;
                h_last = h_new;
                out_reg = h_new;
            }
            unsigned long long v =
                ((unsigned long long)(unsigned)(t + 1) << 32) |
                (unsigned long long)__float_as_uint(h_last);
            htag[(size_t)t * H + u] = v;
        }
    }

    if (lane == 0) {
        out[u]         = out_reg;  // out
        out[H + u]     = h_last;   // h
        out[2 * H + u] = c_reg;    // c
    }
}

extern "C" void kernel_launch(void* const* d_in, const int* in_sizes, int n_in,
                              void* d_out, int out_size)
{
    const int*   tokens = (const int*)  d_in[0];
    const float* h0     = (const float*)d_in[1];
    const float* c0     = (const float*)d_in[2];
    const float* emb    = (const float*)d_in[3];
    const float* Wih    = (const float*)d_in[4];
    const float* Whh    = (const float*)d_in[5];
    const float* bih    = (const float*)d_in[6];
    const float* bhh    = (const float*)d_in[7];
    float* out = (float*)d_out;

    // Reset the tag buffer every launch (deterministic across graph replays).
    void* htag_ptr = nullptr;
    cudaGetSymbolAddress(&htag_ptr, g_htag);
    cudaMemsetAsync(htag_ptr, 0, sizeof(unsigned long long) * SEQL * H);

    dim3 g1(G4 / 64, SEQL / 64);
    xgemm_kernel<<<g1, 256>>>(tokens, emb, Wih, bih, bhh);
    lstm_kernel<<<NCTA, TPB>>>(tokens, h0, c0, Whh, out);
}

// round 5
// speedup vs baseline: 3.0302x; 2.0863x over previous
#include <cuda_runtime.h>
#include <cstdint>

#define H    512
#define G4   2048
#define SEQL 1024
#define EMB  300
#define NCTA 64
#define TPB  256

// Scratch: 8 MB gate-precompute (transposed [t][u][gate]) + 4 MB tagged-h ring.
__device__ float g_xg4[SEQL * G4];
__device__ __align__(16) unsigned long long g_htag[SEQL * H];

// ---------------------------------------------------------------------------
// Kernel 1: xg[t][u][g] = (b_ih[r]+b_hh[r]) + sum_e emb[tok[t]][e]*W_ih[r][e],
// r = g*512+u. 64x64 tile per block, 4x4 micro-tile per thread.
// ---------------------------------------------------------------------------
#define TK 16
__global__ __launch_bounds__(256) void xgemm_kernel(
    const int* __restrict__ tokens,
    const float* __restrict__ emb,
    const float* __restrict__ Wih,
    const float* __restrict__ bih,
    const float* __restrict__ bhh)
{
    __shared__ float Ws[64][TK + 1];
    __shared__ float Xs[64][TK + 1];
    __shared__ int   toks[64];

    const int row0 = blockIdx.x * 64;
    const int t0   = blockIdx.y * 64;
    const int tid  = threadIdx.x;
    const int tx = tid & 15, ty = tid >> 4;

    if (tid < 64) toks[tid] = tokens[t0 + tid];
    __syncthreads();

    float acc[4][4];
#pragma unroll
    for (int i = 0; i < 4; i++)
#pragma unroll
        for (int j = 0; j < 4; j++) acc[i][j] = 0.f;

    const int kk = tid & 15;
    const int ib = tid >> 4;

    for (int k0 = 0; k0 < EMB; k0 += TK) {
#pragma unroll
        for (int q = 0; q < 4; q++) {
            int i = ib + q * 16;
            int e = k0 + kk;
            long widx = (long)(row0 + i) * EMB + (e < EMB ? e : EMB - 1);
            Ws[i][kk] = Wih[widx];
            Xs[i][kk] = (e < EMB) ? emb[(long)toks[i] * EMB + e] : 0.f;
        }
        __syncthreads();
#pragma unroll
        for (int k = 0; k < TK; k++) {
            float a[4], x[4];
#pragma unroll
            for (int i = 0; i < 4; i++) a[i] = Ws[tx * 4 + i][k];
#pragma unroll
            for (int j = 0; j < 4; j++) x[j] = Xs[ty * 4 + j][k];
#pragma unroll
            for (int i = 0; i < 4; i++)
#pragma unroll
                for (int j = 0; j < 4; j++)
                    acc[i][j] += a[i] * x[j];
        }
        __syncthreads();
    }

#pragma unroll
    for (int i = 0; i < 4; i++) {
        int row = row0 + tx * 4 + i;
        float bias = bih[row] + bhh[row];
        int u = row & 511, g = row >> 9;
#pragma unroll
        for (int j = 0; j < 4; j++) {
            int t = t0 + ty * 4 + j;
            g_xg4[(long)t * G4 + u * 4 + g] = acc[i][j] + bias;   // [t][u][gate]
        }
    }
}

// ---------------------------------------------------------------------------
// packed fp32x2 ops (sm_103a; only emitted via PTX)
// ---------------------------------------------------------------------------
__device__ __forceinline__ void ffma2(unsigned long long& d,
                                      unsigned long long a, unsigned long long b)
{
    asm("fma.rn.f32x2 %0, %1, %2, %3;" : "=l"(d) : "l"(a), "l"(b), "l"(d));
}

__device__ __forceinline__ float fast_tanh(float x)
{
    float a = fabsf(x);
    float e = __expf(-2.f * a);
    float r = __fdividef(1.f - e, 1.f + e);
    return copysignf(r, x);
}
__device__ __forceinline__ float fast_sigmoid(float x)
{
    return __fdividef(1.f, 1.f + __expf(-x));
}

// ---------------------------------------------------------------------------
// Kernel 2: persistent LSTM recurrence — R1's proven 3-barrier lockstep
// skeleton, with faster intra-step compute:
//   * dot via fma.rn.f32x2 (32 issues + 8 LDS.64, 18-stride padded smem)
//   * nonlinearity via __expf-based tanh/sigmoid
//   * xg fetched as one LDG.128 per publisher thread, prefetched pre-poll
// 64 CTAs x 256 threads; warp w computes gate (w>>1) rows 4(w&1)..+3 for
// units b*8..b*8+7; tid<8 owns unit b*8+tid (nonlinearity + tagged publish).
// Trailing barrier is load-bearing: it parks all warps so the publisher
// warp's exp/div chain has the SMSP to itself (R2/R3 showed removing it
// costs ~2x).
// ---------------------------------------------------------------------------
// smem h layout: h[k] stored at f(k) = 18*(k>>4) + (k&15)  (max 573 -> 576)
__global__ __launch_bounds__(TPB, 1) void lstm_kernel(
    const int* __restrict__ tokens,
    const float* __restrict__ h0,
    const float* __restrict__ c0,
    const float* __restrict__ Whh,
    float* __restrict__ out)
{
    __shared__ __align__(16) float h_s[576];
    __shared__ float gates_s[32];
    __shared__ int   toks[SEQL];

    const int b    = blockIdx.x;
    const int tid  = threadIdx.x;
    const int w    = tid >> 5;
    const int lane = tid & 31;

    for (int i = tid; i < SEQL; i += TPB) toks[i] = tokens[i];

    // Weights: warp w -> gate g=w>>1, rows rbase..rbase+3; lane covers
    // K in [16*lane, 16*lane+16) as 8 f32x2 pairs.
    const int rbase = (w >> 1) * H + b * 8 + 4 * (w & 1);
    unsigned long long wp[4][8];
#pragma unroll
    for (int i = 0; i < 4; i++) {
        const float* wrow = Whh + (size_t)(rbase + i) * H + 16 * lane;
#pragma unroll
        for (int j = 0; j < 8; j++) {
            float2 f = *(const float2*)(wrow + 2 * j);
            unsigned long long v;
            asm("mov.b64 %0, {%1,%2};" : "=l"(v) : "f"(f.x), "f"(f.y));
            wp[i][j] = v;
        }
    }

    float c_reg = 0.f, h_last = 0.f, out_reg = 0.f;
    if (tid < 8) {
        c_reg  = c0[b * 8 + tid];
        h_last = h0[b * 8 + tid];
    }

    unsigned long long* htag = g_htag;

    for (int t = 0; t < SEQL; t++) {
        // Publisher threads prefetch their 4 gate biases (1 LDG.128),
        // latency hidden behind the poll below.
        float4 xgv = make_float4(0.f, 0.f, 0.f, 0.f);
        if (tid < 8)
            xgv = *(const float4*)(g_xg4 + (size_t)t * G4 + (b * 8 + tid) * 4);

        // Acquire h_{t-1} into padded smem (thread handles k0=2tid, k0+1;
        // both map to consecutive padded slots since k0 is even).
        {
            const int k0 = 2 * tid;
            float* dst = &h_s[18 * (k0 >> 4) + (k0 & 15)];
            if (t == 0) {
                *(float2*)dst = *(const float2*)(h0 + k0);
            } else {
                const unsigned long long* ptr =
                    htag + (size_t)(t - 1) * H + k0;
                unsigned long long v0, v1;
                const unsigned tag = (unsigned)t;
                do {
                    asm volatile("ld.volatile.global.v2.u64 {%0,%1},[%2];"
                                 : "=l"(v0), "=l"(v1) : "l"(ptr));
                } while ((unsigned)(v0 >> 32) != tag ||
                         (unsigned)(v1 >> 32) != tag);
                float2 hv;
                hv.x = __uint_as_float((unsigned)v0);
                hv.y = __uint_as_float((unsigned)v1);
                *(float2*)dst = hv;
            }
        }
        __syncthreads();

        // Dot: 4 gate rows x 16 K per thread, f32x2 FMAs, weights in regs.
        unsigned long long a0 = 0ull, a1 = 0ull, a2 = 0ull, a3 = 0ull;
        const unsigned long long* hb =
            (const unsigned long long*)&h_s[18 * lane];
#pragma unroll
        for (int j = 0; j < 8; j++) {
            unsigned long long hv = hb[j];        // h[16*lane+2j], h[+1]
            ffma2(a0, wp[0][j], hv);
            ffma2(a1, wp[1][j], hv);
            ffma2(a2, wp[2][j], hv);
            ffma2(a3, wp[3][j], hv);
        }
        float acc0, acc1, acc2, acc3;
        {
            float lo, hi;
            asm("mov.b64 {%0,%1}, %2;" : "=f"(lo), "=f"(hi) : "l"(a0)); acc0 = lo + hi;
            asm("mov.b64 {%0,%1}, %2;" : "=f"(lo), "=f"(hi) : "l"(a1)); acc1 = lo + hi;
            asm("mov.b64 {%0,%1}, %2;" : "=f"(lo), "=f"(hi) : "l"(a2)); acc2 = lo + hi;
            asm("mov.b64 {%0,%1}, %2;" : "=f"(lo), "=f"(hi) : "l"(a3)); acc3 = lo + hi;
        }
#pragma unroll
        for (int off = 16; off > 0; off >>= 1) {
            acc0 += __shfl_xor_sync(0xffffffffu, acc0, off);
            acc1 += __shfl_xor_sync(0xffffffffu, acc1, off);
            acc2 += __shfl_xor_sync(0xffffffffu, acc2, off);
            acc3 += __shfl_xor_sync(0xffffffffu, acc3, off);
        }
        if (lane == 0) {
            gates_s[w * 4 + 0] = acc0;
            gates_s[w * 4 + 1] = acc1;
            gates_s[w * 4 + 2] = acc2;
            gates_s[w * 4 + 3] = acc3;
        }
        __syncthreads();

        if (tid < 8) {
            const int k = tid;
            float si = fast_sigmoid(gates_s[k]      + xgv.x);
            float sf = fast_sigmoid(gates_s[8 + k]  + xgv.y);
            float tg = fast_tanh   (gates_s[16 + k] + xgv.z);
            float so = fast_sigmoid(gates_s[24 + k] + xgv.w);
            float c_new = sf * c_reg + si * tg;
            float h_new = so * fast_tanh(c_new);
            if (toks[t] != 1) {                 // PAD_IDX == 1
                c_reg  = c_new;
                h_last = h_new;
                out_reg = h_new;
            }
            unsigned long long v =
                ((unsigned long long)(unsigned)(t + 1) << 32) |
                (unsigned long long)__float_as_uint(h_last);
            htag[(size_t)t * H + b * 8 + k] = v;
        }
        __syncthreads();   // park everyone: publisher warp owns its SMSP
    }

    if (tid < 8) {
        out[b * 8 + tid]         = out_reg;  // out
        out[H + b * 8 + tid]     = h_last;   // h
        out[2 * H + b * 8 + tid] = c_reg;    // c
    }
}

extern "C" void kernel_launch(void* const* d_in, const int* in_sizes, int n_in,
                              void* d_out, int out_size)
{
    const int*   tokens = (const int*)  d_in[0];
    const float* h0     = (const float*)d_in[1];
    const float* c0     = (const float*)d_in[2];
    const float* emb    = (const float*)d_in[3];
    const float* Wih    = (const float*)d_in[4];
    const float* Whh    = (const float*)d_in[5];
    const float* bih    = (const float*)d_in[6];
    const float* bhh    = (const float*)d_in[7];
    float* out = (float*)d_out;

    // Reset the tag buffer every launch (deterministic across graph replays).
    void* htag_ptr = nullptr;
    cudaGetSymbolAddress(&htag_ptr, g_htag);
    cudaMemsetAsync(htag_ptr, 0, sizeof(unsigned long long) * SEQL * H);

    dim3 g1(G4 / 64, SEQL / 64);
    xgemm_kernel<<<g1, 256>>>(tokens, emb, Wih, bih, bhh);
    lstm_kernel<<<NCTA, TPB>>>(tokens, h0, c0, Whh, out);
}